// round 15
// baseline (speedup 1.0000x reference)
#include <cuda_runtime.h>
#include <cuda_fp16.h>
#include <cstdint>

// out = concat(x, y, outer(x,y)) @ W^T, two kernels:
//  1) lin_pipe  : k < 1024 passthrough (proven).
//  2) quad_fact : bilinear FACTORIZED (out += sum_i x_i * (y @ W_i^T)).
//     THIS ROUND: BM=64 / 256-thread CTAs, ~109KB smem, 2 CTAs per SM
//     (grid 16x16 = one wave at 2/SM). Same per-SM pipe work as R14 but the
//     two co-resident CTAs desynchronize barrier/producer bubbles, and the
//     barrier scope halves. x-slab stored fp16 (numerically identical).
//     Per-element op order unchanged -> rel_err must stay 4.137952e-4.

namespace {

constexpr int    kN1  = 512;
constexpr int    kOUT = 1024;
constexpr size_t kK   = 263168;

__device__ __forceinline__ uint32_t smem_u32(const void* p) {
  uint32_t a;
  asm("{ .reg .u64 t; cvta.to.shared.u64 t, %1; cvt.u32.u64 %0, t; }"
      : "=r"(a) : "l"(p));
  return a;
}
__device__ __forceinline__ void ldx4(uint32_t r[4], uint32_t addr) {
  asm volatile(
      "ldmatrix.sync.aligned.m8n8.x4.shared.b16 {%0,%1,%2,%3}, [%4];"
      : "=r"(r[0]), "=r"(r[1]), "=r"(r[2]), "=r"(r[3]) : "r"(addr));
}
__device__ __forceinline__ void mma16(float c[4], const uint32_t a[4],
                                      uint32_t b0, uint32_t b1) {
  asm volatile(
      "mma.sync.aligned.m16n8k16.row.col.f32.f16.f16.f32 "
      "{%0,%1,%2,%3}, {%4,%5,%6,%7}, {%8,%9}, {%0,%1,%2,%3};"
      : "+f"(c[0]), "+f"(c[1]), "+f"(c[2]), "+f"(c[3])
      : "r"(a[0]), "r"(a[1]), "r"(a[2]), "r"(a[3]), "r"(b0), "r"(b1));
}
__device__ __forceinline__ void sts128(uint32_t a, uint32_t v0, uint32_t v1,
                                       uint32_t v2, uint32_t v3) {
  asm volatile("st.shared.v4.b32 [%0], {%1,%2,%3,%4};"
               :: "r"(a), "r"(v0), "r"(v1), "r"(v2), "r"(v3) : "memory");
}
__device__ __forceinline__ void sts16(uint32_t a, uint32_t v) {
  asm volatile("st.shared.u16 [%0], %1;" :: "r"(a), "r"(v) : "memory");
}
__device__ __forceinline__ uint32_t lds16_dup(uint32_t a) {
  uint32_t v;
  asm volatile("ld.shared.u16 %0, [%1];" : "=r"(v) : "r"(a));
  return v | (v << 16);
}
__device__ __forceinline__ uint32_t pack_h2(float v0, float v1) {
  __half2 h = __floats2half2_rn(v0, v1);
  return *reinterpret_cast<uint32_t*>(&h);
}
__device__ __forceinline__ void split_h2(float v0, float v1, uint32_t& h,
                                         uint32_t& l) {
  __half2 hh = __floats2half2_rn(v0, v1);
  h = *reinterpret_cast<uint32_t*>(&hh);
  l = pack_h2(v0 - __low2float(hh), v1 - __high2float(hh));
}
__device__ __forceinline__ uint32_t hmul2u(uint32_t a, uint32_t b) {
  __half2 r = __hmul2(*reinterpret_cast<__half2*>(&a),
                      *reinterpret_cast<__half2*>(&b));
  return *reinterpret_cast<uint32_t*>(&r);
}

// ======================= linear part (k<1024): proven pipeline ==============
constexpr int L_LDA = 80, L_SZA = 128 * L_LDA, L_SZW = 128 * L_LDA;
constexpr int L_STAGE = L_SZA + 2 * L_SZW;
constexpr int LNH = 16;

__global__ void __launch_bounds__(256, 1)
lin_pipe(const float* __restrict__ x, const float* __restrict__ y,
         const float* __restrict__ W, float* __restrict__ out) {
  __shared__ __align__(16) uint8_t sm[2 * L_STAGE];
  const uint32_t sb = smem_u32(sm);

  const int tid = threadIdx.x, lane = tid & 31, warp = tid >> 5;
  const int wm = warp >> 2, wn = warp & 3;
  const int b0 = (blockIdx.x >> 1) * 128;
  const int half = blockIdx.x & 1;
  const int o0 = blockIdx.y * 128;
  const int gbase = half * LNH;

  const int prow = tid >> 1, phh = tid & 1;
  const float* __restrict__ xrow = x + (size_t)(b0 + prow) * kN1;
  const float* __restrict__ yrow = y + (size_t)(b0 + prow) * kN1;
  const float* __restrict__ wsrc = W + (size_t)(o0 + prow) * kK + phh * 16;
  const uint32_t pSt = prow * L_LDA + phh * 32;

  const uint32_t aoff =
      (uint32_t)((wm * 64 + (lane & 15)) * L_LDA + (lane >> 4) * 16);
  const uint32_t boff =
      (uint32_t)((wn * 32 + (lane & 7) + ((lane >> 4) & 1) * 8) * L_LDA +
                 ((lane >> 3) & 1) * 16);
  const int g = lane >> 2, t = lane & 3;

  float acc[4][4][4];
#pragma unroll
  for (int mt = 0; mt < 4; mt++)
#pragma unroll
    for (int nt = 0; nt < 4; nt++)
#pragma unroll
      for (int r = 0; r < 4; r++) acc[mt][nt][r] = 0.f;

  float4 av[4], wv[4];

  {  // chunk 0 into stage 0
    const int gc = gbase;
    const float* asrc = (gc < 16) ? (xrow + gc * 32 + phh * 16)
                                  : (yrow + (gc - 16) * 32 + phh * 16);
#pragma unroll
    for (int j = 0; j < 4; j++) av[j] = *(const float4*)(asrc + 4 * j);
    const float* wp = wsrc + (size_t)gc * 32;
#pragma unroll
    for (int j = 0; j < 4; j++) wv[j] = *(const float4*)(wp + 4 * j);

    uint32_t pA[8], pWh[8], pWl[8];
#pragma unroll
    for (int j = 0; j < 4; j++) {
      pA[2 * j]     = pack_h2(av[j].x, av[j].y);
      pA[2 * j + 1] = pack_h2(av[j].z, av[j].w);
      split_h2(wv[j].x, wv[j].y, pWh[2 * j], pWl[2 * j]);
      split_h2(wv[j].z, wv[j].w, pWh[2 * j + 1], pWl[2 * j + 1]);
    }
    sts128(sb + pSt, pA[0], pA[1], pA[2], pA[3]);
    sts128(sb + pSt + 16, pA[4], pA[5], pA[6], pA[7]);
    sts128(sb + L_SZA + pSt, pWh[0], pWh[1], pWh[2], pWh[3]);
    sts128(sb + L_SZA + pSt + 16, pWh[4], pWh[5], pWh[6], pWh[7]);
    sts128(sb + L_SZA + L_SZW + pSt, pWl[0], pWl[1], pWl[2], pWl[3]);
    sts128(sb + L_SZA + L_SZW + pSt + 16, pWl[4], pWl[5], pWl[6], pWl[7]);
  }
  __syncthreads();

  for (int ic = 0; ic < LNH; ic++) {
    const uint32_t rs = sb + (uint32_t)(ic & 1) * L_STAGE;
    const uint32_t ws = sb + (uint32_t)((ic + 1) & 1) * L_STAGE;
    const bool more = (ic + 1 < LNH);

    if (more) {
      const int gc = gbase + ic + 1;
      const float* asrc = (gc < 16) ? (xrow + gc * 32 + phh * 16)
                                    : (yrow + (gc - 16) * 32 + phh * 16);
#pragma unroll
      for (int j = 0; j < 4; j++) av[j] = *(const float4*)(asrc + 4 * j);
      const float* wp = wsrc + (size_t)gc * 32;
#pragma unroll
      for (int j = 0; j < 4; j++) wv[j] = *(const float4*)(wp + 4 * j);
    }

#pragma unroll
    for (int ks = 0; ks < 2; ks++) {
      const uint32_t ko = ks * 32;
      uint32_t aH[4][4], bH[2][4], bL[2][4];
#pragma unroll
      for (int mt = 0; mt < 4; mt++)
        ldx4(aH[mt], rs + aoff + mt * (16 * L_LDA) + ko);
#pragma unroll
      for (int p = 0; p < 2; p++) {
        ldx4(bH[p], rs + L_SZA + boff + p * (16 * L_LDA) + ko);
        ldx4(bL[p], rs + L_SZA + L_SZW + boff + p * (16 * L_LDA) + ko);
      }
#pragma unroll
      for (int mt = 0; mt < 4; mt++)
#pragma unroll
        for (int nt = 0; nt < 4; nt++) {
          const int p = nt >> 1, o = (nt & 1) * 2;
          mma16(acc[mt][nt], aH[mt], bH[p][o], bH[p][o + 1]);
          mma16(acc[mt][nt], aH[mt], bL[p][o], bL[p][o + 1]);
        }
    }

    if (more) {
      uint32_t pA[8], pWh[8], pWl[8];
#pragma unroll
      for (int j = 0; j < 4; j++) {
        pA[2 * j]     = pack_h2(av[j].x, av[j].y);
        pA[2 * j + 1] = pack_h2(av[j].z, av[j].w);
        split_h2(wv[j].x, wv[j].y, pWh[2 * j], pWl[2 * j]);
        split_h2(wv[j].z, wv[j].w, pWh[2 * j + 1], pWl[2 * j + 1]);
      }
      sts128(ws + pSt, pA[0], pA[1], pA[2], pA[3]);
      sts128(ws + pSt + 16, pA[4], pA[5], pA[6], pA[7]);
      sts128(ws + L_SZA + pSt, pWh[0], pWh[1], pWh[2], pWh[3]);
      sts128(ws + L_SZA + pSt + 16, pWh[4], pWh[5], pWh[6], pWh[7]);
      sts128(ws + L_SZA + L_SZW + pSt, pWl[0], pWl[1], pWl[2], pWl[3]);
      sts128(ws + L_SZA + L_SZW + pSt + 16, pWl[4], pWl[5], pWl[6], pWl[7]);
    }
    __syncthreads();
  }

#pragma unroll
  for (int mt = 0; mt < 4; mt++)
#pragma unroll
    for (int nt = 0; nt < 4; nt++) {
      const int r0 = b0 + wm * 64 + mt * 16 + g;
      const int c0 = o0 + wn * 32 + nt * 8 + 2 * t;
      atomicAdd(out + (size_t)r0 * kOUT + c0, acc[mt][nt][0]);
      atomicAdd(out + (size_t)r0 * kOUT + c0 + 1, acc[mt][nt][1]);
      atomicAdd(out + (size_t)(r0 + 8) * kOUT + c0, acc[mt][nt][2]);
      atomicAdd(out + (size_t)(r0 + 8) * kOUT + c0 + 1, acc[mt][nt][3]);
    }
}

// ===== bilinear: factorized, BM=64, 256 threads, 2 CTAs/SM ==================
constexpr int F_LDY  = 1040;
constexpr int F_YH   = 64 * F_LDY;               // 66560
constexpr int F_XS   = 64 * 128;                 // 8192 (64 i x 64 rows, fp16)
constexpr int F_LDW  = 144;
constexpr int F_WT   = 64 * F_LDW;               // 9216
constexpr int F_STG  = 2 * F_WT;                 // 2 i's per stage
constexpr int F_SMEM = F_YH + F_XS + 2 * F_STG;  // 111616
constexpr int NSTG   = 2048;

__global__ void __launch_bounds__(256, 2)
quad_fact(const float* __restrict__ x, const float* __restrict__ y,
          const float* __restrict__ W, float* __restrict__ out) {
  extern __shared__ __align__(16) uint8_t dsm[];
  const uint32_t sY = smem_u32(dsm);
  const uint32_t sX = sY + F_YH;
  const uint32_t sW0 = sX + F_XS;

  const int tid = threadIdx.x, lane = tid & 31, warp = tid >> 5;
  const int wm = warp & 1, wn = warp >> 1;  // 2m x 4n, warp tile 32x16
  const int b0 = blockIdx.x * 64, o0 = blockIdx.y * 64;
  const int g = lane >> 2, t = lane & 3;

  // ---- stage Y as fp16 (once): 4 threads/row, 128 cols each ----
  {
    const int row = tid >> 2, h = tid & 3;
    const float* yr = y + (size_t)(b0 + row) * kN1 + h * 128;
    const uint32_t st = sY + row * F_LDY + h * 256;
#pragma unroll 4
    for (int c = 0; c < 128; c += 8) {
      float4 f0 = *(const float4*)(yr + c);
      float4 f1 = *(const float4*)(yr + c + 4);
      sts128(st + c * 2, pack_h2(f0.x, f0.y), pack_h2(f0.z, f0.w),
             pack_h2(f1.x, f1.y), pack_h2(f1.z, f1.w));
    }
  }

  // ---- W producer: 4 threads per o-row, 16 k-floats each ----
  const int prow = tid >> 2, pq = (tid & 2) * 8;  // (tid&3): pq pairs below
  const int pq4 = (tid & 3) * 16;
  const float* __restrict__ wbase = W + (size_t)(o0 + prow) * kK + pq4 + 1024;
  const uint32_t wSt = prow * F_LDW + pq4 * 2;
  (void)pq;

  // ---- x-slab staging: 4 threads/row, 16 i each, fp16 [i][row] ----
  const int xrw = tid >> 2, xih = tid & 3;
  const float* __restrict__ xbase = x + (size_t)(b0 + xrw) * kN1 + xih * 16;

  const uint32_t aoff =
      (uint32_t)((wm * 32 + (lane & 15)) * F_LDY + (lane >> 4) * 16);
  const uint32_t boff =
      (uint32_t)((wn * 16 + (lane & 7) + ((lane >> 4) & 1) * 8) * F_LDW +
                 ((lane >> 3) & 1) * 16);

  float acc[2][2][4], tot[2][2][4];
#pragma unroll
  for (int mt = 0; mt < 2; mt++)
#pragma unroll
    for (int nt = 0; nt < 2; nt++)
#pragma unroll
      for (int r = 0; r < 4; r++) { acc[mt][nt][r] = 0.f; tot[mt][nt][r] = 0.f; }

  // ---- prologue: x-slab iblk 0 + W stage 0 (i = 0, 1) ----
  {
#pragma unroll
    for (int j = 0; j < 16; j += 4) {
      float4 v = *(const float4*)(xbase + j);
      const uint32_t a = sX + (xih * 16 + j) * 128 + xrw * 2;
      sts16(a,       __half_as_ushort(__float2half_rn(v.x)));
      sts16(a + 128, __half_as_ushort(__float2half_rn(v.y)));
      sts16(a + 256, __half_as_ushort(__float2half_rn(v.z)));
      sts16(a + 384, __half_as_ushort(__float2half_rn(v.w)));
    }
#pragma unroll
    for (int u = 0; u < 2; u++) {
      const float* wp = wbase + (size_t)u * 512;
      float4 v0 = *(const float4*)(wp), v1 = *(const float4*)(wp + 4);
      float4 v2 = *(const float4*)(wp + 8), v3 = *(const float4*)(wp + 12);
      sts128(sW0 + u * F_WT + wSt, pack_h2(v0.x, v0.y), pack_h2(v0.z, v0.w),
             pack_h2(v1.x, v1.y), pack_h2(v1.z, v1.w));
      sts128(sW0 + u * F_WT + wSt + 16, pack_h2(v2.x, v2.y), pack_h2(v2.z, v2.w),
             pack_h2(v3.x, v3.y), pack_h2(v3.z, v3.w));
    }
  }
  __syncthreads();

  uint32_t yf[2][4][4];  // [mt][ks][reg]

  for (int s = 0; s < NSTG; s++) {
    const int c0i = 2 * s;

    if ((s & 255) == 0) {  // new j-block: reload Y fragments (sY static)
      const int jb = s >> 8;
#pragma unroll
      for (int mt = 0; mt < 2; mt++)
#pragma unroll
        for (int ks = 0; ks < 4; ks++)
          ldx4(yf[mt][ks], sY + aoff + jb * 128 + mt * (16 * F_LDY) + ks * 32);
    }
    if ((s & 31) == 0 && s) {  // new 64-i block: restage x-slab
      const int iblk = (c0i & 511) >> 6;
#pragma unroll
      for (int j = 0; j < 16; j += 4) {
        float4 v = *(const float4*)(xbase + iblk * 64 + j);
        const uint32_t a = sX + (xih * 16 + j) * 128 + xrw * 2;
        sts16(a,       __half_as_ushort(__float2half_rn(v.x)));
        sts16(a + 128, __half_as_ushort(__float2half_rn(v.y)));
        sts16(a + 256, __half_as_ushort(__float2half_rn(v.z)));
        sts16(a + 384, __half_as_ushort(__float2half_rn(v.w)));
      }
      __syncthreads();
    }

    const uint32_t rs = sW0 + (uint32_t)(s & 1) * F_STG;
    const uint32_t ws = sW0 + (uint32_t)((s + 1) & 1) * F_STG;
    const bool more = (s + 1 < NSTG);
    const int c2 = 2 * (s + 1);
    const float* wnext =
        more ? (wbase + (size_t)(c2 & 511) * 512 + (c2 >> 9) * 64) : wbase;

    // ---- xsd for both i's up front (fp16 slab; dup == prior numerics) ----
    uint32_t xsd[2][2][2];  // [u][mt][half]
#pragma unroll
    for (int u = 0; u < 2; u++) {
      const uint32_t xb =
          sX + (uint32_t)((c0i + u) & 63) * 128 + (wm * 32) * 2;
#pragma unroll
      for (int mt = 0; mt < 2; mt++) {
        xsd[u][mt][0] = lds16_dup(xb + (mt * 16 + g) * 2);
        xsd[u][mt][1] = lds16_dup(xb + (mt * 16 + g + 8) * 2);
      }
    }

    // ---- LDG next-stage i0 (lands during u=0 MMA) ----
    float4 wva[4];
    if (more) {
      wva[0] = *(const float4*)(wnext);
      wva[1] = *(const float4*)(wnext + 4);
      wva[2] = *(const float4*)(wnext + 8);
      wva[3] = *(const float4*)(wnext + 12);
    }

    // ---- u = 0 MMA ----
#pragma unroll
    for (int ks = 0; ks < 4; ks++) {
      uint32_t b[4];
      ldx4(b, rs + boff + ks * 32);
#pragma unroll
      for (int mt = 0; mt < 2; mt++) {
        uint32_t as[4];
        as[0] = hmul2u(yf[mt][ks][0], xsd[0][mt][0]);
        as[1] = hmul2u(yf[mt][ks][1], xsd[0][mt][1]);
        as[2] = hmul2u(yf[mt][ks][2], xsd[0][mt][0]);
        as[3] = hmul2u(yf[mt][ks][3], xsd[0][mt][1]);
        mma16(acc[mt][0], as, b[0], b[1]);
        mma16(acc[mt][1], as, b[2], b[3]);
      }
    }

    // ---- STS next i0; LDG next i1 (lands during u=1 MMA) ----
    float4 wvb[4];
    if (more) {
      sts128(ws + wSt, pack_h2(wva[0].x, wva[0].y), pack_h2(wva[0].z, wva[0].w),
             pack_h2(wva[1].x, wva[1].y), pack_h2(wva[1].z, wva[1].w));
      sts128(ws + wSt + 16, pack_h2(wva[2].x, wva[2].y), pack_h2(wva[2].z, wva[2].w),
             pack_h2(wva[3].x, wva[3].y), pack_h2(wva[3].z, wva[3].w));
      wvb[0] = *(const float4*)(wnext + 512);
      wvb[1] = *(const float4*)(wnext + 516);
      wvb[2] = *(const float4*)(wnext + 520);
      wvb[3] = *(const float4*)(wnext + 524);
    }

    // ---- u = 1 MMA ----
#pragma unroll
    for (int ks = 0; ks < 4; ks++) {
      uint32_t b[4];
      ldx4(b, rs + F_WT + boff + ks * 32);
#pragma unroll
      for (int mt = 0; mt < 2; mt++) {
        uint32_t as[4];
        as[0] = hmul2u(yf[mt][ks][0], xsd[1][mt][0]);
        as[1] = hmul2u(yf[mt][ks][1], xsd[1][mt][1]);
        as[2] = hmul2u(yf[mt][ks][2], xsd[1][mt][0]);
        as[3] = hmul2u(yf[mt][ks][3], xsd[1][mt][1]);
        mma16(acc[mt][0], as, b[0], b[1]);
        mma16(acc[mt][1], as, b[2], b[3]);
      }
    }

    // ---- bounded RZ chain (64 adds) -> RN totals (i1 = 2s+1) ----
    if (((c0i + 1) & 15) == 15) {
#pragma unroll
      for (int mt = 0; mt < 2; mt++)
#pragma unroll
        for (int nt = 0; nt < 2; nt++)
#pragma unroll
          for (int r = 0; r < 4; r++) {
            tot[mt][nt][r] += acc[mt][nt][r];
            acc[mt][nt][r] = 0.f;
          }
    }

    // ---- STS next i1, then stage barrier ----
    if (more) {
      sts128(ws + F_WT + wSt, pack_h2(wvb[0].x, wvb[0].y), pack_h2(wvb[0].z, wvb[0].w),
             pack_h2(wvb[1].x, wvb[1].y), pack_h2(wvb[1].z, wvb[1].w));
      sts128(ws + F_WT + wSt + 16, pack_h2(wvb[2].x, wvb[2].y), pack_h2(wvb[2].z, wvb[2].w),
             pack_h2(wvb[3].x, wvb[3].y), pack_h2(wvb[3].z, wvb[3].w));
    }
    __syncthreads();
  }

  // ---- epilogue: exclusive ownership, non-atomic += ----
#pragma unroll
  for (int mt = 0; mt < 2; mt++)
#pragma unroll
    for (int nt = 0; nt < 2; nt++) {
      const int r0 = b0 + wm * 32 + mt * 16 + g;
      const int c0 = o0 + wn * 16 + nt * 8 + 2 * t;
      out[(size_t)r0 * kOUT + c0]           += tot[mt][nt][0];
      out[(size_t)r0 * kOUT + c0 + 1]       += tot[mt][nt][1];
      out[(size_t)(r0 + 8) * kOUT + c0]     += tot[mt][nt][2];
      out[(size_t)(r0 + 8) * kOUT + c0 + 1] += tot[mt][nt][3];
    }
}

}  // namespace

extern "C" void kernel_launch(void* const* d_in, const int* in_sizes, int n_in,
                              void* d_out, int out_size) {
  (void)in_sizes; (void)n_in; (void)out_size;
  const float* x = (const float*)d_in[0];
  const float* y = (const float*)d_in[1];
  const float* W = (const float*)d_in[2];
  float* out = (float*)d_out;

  cudaFuncSetAttribute(quad_fact, cudaFuncAttributeMaxDynamicSharedMemorySize,
                       F_SMEM);

  cudaMemsetAsync(out, 0, (size_t)1024 * kOUT * sizeof(float));
  lin_pipe<<<dim3(16, 8), 256>>>(x, y, W, out);             // k < 1024
  quad_fact<<<dim3(16, 16), 256, F_SMEM>>>(x, y, W, out);   // bilinear part
}